// round 14
// baseline (speedup 1.0000x reference)
#include <cuda_runtime.h>
#include <cuda_bf16.h>

// GCNConv (1 in/out feature, self-loops, symmetric norm) + sigmoid.
// out[d] = sigmoid( dinv[d]*( SUM_{e:dst=d} dinv[src]*x[src]*W + dinv[d]*x[d]*W ) + b )
//
// CONVERGED edge-side (R1-R13): scatter = 2 L1tex wf/edge -> ~232us (at cap),
// degree = 1 wf/edge -> ~128us (at RED-issue floor), TPBE=128 / 4 edges/thread
// measured optimal; fusion/binning/privatization all measured worse.
// R14: widen node-side kernels to 8 elem/thread (2 independent float4 chains)
// to lift their MLP - they are issue-limited (k_final 7.5us vs ~5us floor).

#define MAXN 1048576

__device__ int   g_ideg[MAXN];   // in-degree; ==0 at entry (restored by k_final)
__device__ float g_y[MAXN];      // x * W * rsqrt(deg)
__device__ float g_S[MAXN];      // edge accumulator; ==0 at entry (restored)

// ---------------------------------------------------------------------------
// Degree: 4 edges/thread (one int4 coalesced read), 4 REDs (L2-resident).
__global__ void k_degree(const int* __restrict__ dst, int e4, int e) {
    int i = blockIdx.x * blockDim.x + threadIdx.x;
    if (i < e4) {
        int4 d = reinterpret_cast<const int4*>(dst)[i];
        atomicAdd(&g_ideg[d.x], 1);
        atomicAdd(&g_ideg[d.y], 1);
        atomicAdd(&g_ideg[d.z], 1);
        atomicAdd(&g_ideg[d.w], 1);
    }
    int t = e4 * 4 + i;
    if (i < (e - e4 * 4)) {
        atomicAdd(&g_ideg[dst[t]], 1);
    }
}

// ---------------------------------------------------------------------------
// Per-node: y = x*W*rsqrt(deg+1).  8 elements/thread (2 float4 chains).
__global__ void k_node(const float* __restrict__ x,
                       const float* __restrict__ W, int n8) {
    int i = blockIdx.x * blockDim.x + threadIdx.x;
    if (i < n8) {
        float w = __ldg(W);
        int4   dga = reinterpret_cast<const int4*>(g_ideg)[i * 2];
        int4   dgb = reinterpret_cast<const int4*>(g_ideg)[i * 2 + 1];
        float4 xa  = reinterpret_cast<const float4*>(x)[i * 2];
        float4 xb  = reinterpret_cast<const float4*>(x)[i * 2 + 1];
        float4 ya, yb;
        ya.x = xa.x * w * rsqrtf((float)(dga.x + 1));
        ya.y = xa.y * w * rsqrtf((float)(dga.y + 1));
        ya.z = xa.z * w * rsqrtf((float)(dga.z + 1));
        ya.w = xa.w * w * rsqrtf((float)(dga.w + 1));
        yb.x = xb.x * w * rsqrtf((float)(dgb.x + 1));
        yb.y = xb.y * w * rsqrtf((float)(dgb.y + 1));
        yb.z = xb.z * w * rsqrtf((float)(dgb.z + 1));
        yb.w = xb.w * w * rsqrtf((float)(dgb.w + 1));
        reinterpret_cast<float4*>(g_y)[i * 2]     = ya;
        reinterpret_cast<float4*>(g_y)[i * 2 + 1] = yb;
    }
}
__global__ void k_node_tail(const float* __restrict__ x,
                            const float* __restrict__ W, int n8, int n) {
    int i = n8 * 8 + blockIdx.x * blockDim.x + threadIdx.x;
    if (i < n) {
        g_y[i] = x[i] * __ldg(W) * rsqrtf((float)(g_ideg[i] + 1));
    }
}

// ---------------------------------------------------------------------------
// Scatter: 4 edges/thread. Gathers issued before REDs (MLP=4 per thread).
__global__ void k_scatter(const int* __restrict__ src,
                          const int* __restrict__ dst, int e4, int e) {
    int i = blockIdx.x * blockDim.x + threadIdx.x;
    if (i < e4) {
        int4 s = reinterpret_cast<const int4*>(src)[i];
        int4 d = reinterpret_cast<const int4*>(dst)[i];
        float va = __ldg(&g_y[s.x]);
        float vb = __ldg(&g_y[s.y]);
        float vc = __ldg(&g_y[s.z]);
        float vd = __ldg(&g_y[s.w]);
        atomicAdd(&g_S[d.x], va);
        atomicAdd(&g_S[d.y], vb);
        atomicAdd(&g_S[d.z], vc);
        atomicAdd(&g_S[d.w], vd);
    }
    int t = e4 * 4 + i;
    if (i < (e - e4 * 4)) {
        atomicAdd(&g_S[dst[t]], __ldg(&g_y[src[t]]));
    }
}

// ---------------------------------------------------------------------------
// Finalize: out = sigmoid(rsqrt(deg+1)*(S + y) + b); restore ideg==0 / S==0.
// 8 elements/thread (2 independent float4 chains) for MLP.
__global__ void k_final(float* __restrict__ out,
                        const float* __restrict__ b, int n8) {
    int i = blockIdx.x * blockDim.x + threadIdx.x;
    if (i < n8) {
        float bb = __ldg(b);
        int4   dga = reinterpret_cast<const int4*>(g_ideg)[i * 2];
        int4   dgb = reinterpret_cast<const int4*>(g_ideg)[i * 2 + 1];
        float4 sa  = reinterpret_cast<const float4*>(g_S)[i * 2];
        float4 sb  = reinterpret_cast<const float4*>(g_S)[i * 2 + 1];
        float4 ya  = reinterpret_cast<const float4*>(g_y)[i * 2];
        float4 yb  = reinterpret_cast<const float4*>(g_y)[i * 2 + 1];
        float4 oa, ob;
        float z0 = rsqrtf((float)(dga.x + 1)) * (sa.x + ya.x) + bb;
        float z1 = rsqrtf((float)(dga.y + 1)) * (sa.y + ya.y) + bb;
        float z2 = rsqrtf((float)(dga.z + 1)) * (sa.z + ya.z) + bb;
        float z3 = rsqrtf((float)(dga.w + 1)) * (sa.w + ya.w) + bb;
        float z4 = rsqrtf((float)(dgb.x + 1)) * (sb.x + yb.x) + bb;
        float z5 = rsqrtf((float)(dgb.y + 1)) * (sb.y + yb.y) + bb;
        float z6 = rsqrtf((float)(dgb.z + 1)) * (sb.z + yb.z) + bb;
        float z7 = rsqrtf((float)(dgb.w + 1)) * (sb.w + yb.w) + bb;
        oa.x = 1.0f / (1.0f + __expf(-z0));
        oa.y = 1.0f / (1.0f + __expf(-z1));
        oa.z = 1.0f / (1.0f + __expf(-z2));
        oa.w = 1.0f / (1.0f + __expf(-z3));
        ob.x = 1.0f / (1.0f + __expf(-z4));
        ob.y = 1.0f / (1.0f + __expf(-z5));
        ob.z = 1.0f / (1.0f + __expf(-z6));
        ob.w = 1.0f / (1.0f + __expf(-z7));
        reinterpret_cast<float4*>(out)[i * 2]     = oa;
        reinterpret_cast<float4*>(out)[i * 2 + 1] = ob;
        reinterpret_cast<int4*>(g_ideg)[i * 2]      = make_int4(0, 0, 0, 0);
        reinterpret_cast<int4*>(g_ideg)[i * 2 + 1]  = make_int4(0, 0, 0, 0);
        reinterpret_cast<float4*>(g_S)[i * 2]       = make_float4(0.f, 0.f, 0.f, 0.f);
        reinterpret_cast<float4*>(g_S)[i * 2 + 1]   = make_float4(0.f, 0.f, 0.f, 0.f);
    }
}
__global__ void k_final_tail(float* __restrict__ out,
                             const float* __restrict__ b, int n8, int n) {
    int i = n8 * 8 + blockIdx.x * blockDim.x + threadIdx.x;
    if (i < n) {
        float z = rsqrtf((float)(g_ideg[i] + 1)) * (g_S[i] + g_y[i]) + __ldg(b);
        out[i] = 1.0f / (1.0f + __expf(-z));
        g_ideg[i] = 0;
        g_S[i] = 0.0f;
    }
}

// ---------------------------------------------------------------------------
extern "C" void kernel_launch(void* const* d_in, const int* in_sizes, int n_in,
                              void* d_out, int out_size) {
    const float* x    = (const float*)d_in[0];
    const int*   eidx = (const int*)  d_in[1];
    const float* W    = (const float*)d_in[2];
    const float* b    = (const float*)d_in[3];
    float* out = (float*)d_out;

    int n = in_sizes[0];
    int e = in_sizes[1] / 2;
    const int* src = eidx;
    const int* dst = eidx + e;

    int n8 = n / 8;
    int e4 = e / 4;

    const int TPBN = 256;   // node-side kernels
    const int TPBE = 128;   // edge kernels: measured optimum
    int gn8 = (n8 + TPBN - 1) / TPBN;
    int ge4 = (e4 + TPBE - 1) / TPBE;

    k_degree <<<ge4, TPBE>>>(dst, e4, e);
    k_node   <<<gn8, TPBN>>>(x, W, n8);
    if (n % 8) k_node_tail<<<1, 256>>>(x, W, n8, n);
    k_scatter<<<ge4, TPBE>>>(src, dst, e4, e);
    k_final  <<<gn8, TPBN>>>(out, b, n8);
    if (n % 8) k_final_tail<<<1, 256>>>(out, b, n8, n);
}

// round 15
// speedup vs baseline: 1.0072x; 1.0072x over previous
#include <cuda_runtime.h>
#include <cuda_bf16.h>

// GCNConv (1 in/out feature, self-loops, symmetric norm) + sigmoid.
// out[d] = sigmoid( dinv[d]*( SUM_{e:dst=d} dinv[src]*x[src]*W + dinv[d]*x[d]*W ) + b )
//
// FINAL (converged R1-R14). Model: edge passes are L1tex-wavefront bound at
// ~1 wf/cyc/SM: scatter = 2 wf/edge (gather+RED) -> ~232us (at LTS cap),
// degree = 1 wf/edge -> ~128us (at RED-issue floor). Node/final/gaps ~25us.
// Composed floor ~380us; this configuration measures 384.6us (~99%).
// Measured optima: TPBE=128, 4 edges/thread, 4 node-elems/thread, discrete
// kernels. Refuted: fusion (+157us), binning (+275us), wider unrolls, TPB
// 64/256/512, node 8-wide (occupancy collapse).

#define MAXN 1048576

__device__ int   g_ideg[MAXN];   // in-degree; ==0 at entry (restored by k_final)
__device__ float g_y[MAXN];      // x * W * rsqrt(deg)
__device__ float g_S[MAXN];      // edge accumulator; ==0 at entry (restored)

// ---------------------------------------------------------------------------
// Degree: 4 edges/thread (one int4 coalesced read), 4 REDs (L2-resident).
__global__ void k_degree(const int* __restrict__ dst, int e4, int e) {
    int i = blockIdx.x * blockDim.x + threadIdx.x;
    if (i < e4) {
        int4 d = reinterpret_cast<const int4*>(dst)[i];
        atomicAdd(&g_ideg[d.x], 1);
        atomicAdd(&g_ideg[d.y], 1);
        atomicAdd(&g_ideg[d.z], 1);
        atomicAdd(&g_ideg[d.w], 1);
    }
    int t = e4 * 4 + i;
    if (i < (e - e4 * 4)) {
        atomicAdd(&g_ideg[dst[t]], 1);
    }
}

// ---------------------------------------------------------------------------
// Per-node: y = x*W*rsqrt(deg+1).  (S already zero; restored by k_final.)
__global__ void k_node(const float* __restrict__ x,
                       const float* __restrict__ W, int n4) {
    int i = blockIdx.x * blockDim.x + threadIdx.x;
    if (i < n4) {
        float w  = __ldg(W);
        int4  dg = reinterpret_cast<const int4*>(g_ideg)[i];
        float4 xv = reinterpret_cast<const float4*>(x)[i];
        float4 yv;
        yv.x = xv.x * w * rsqrtf((float)(dg.x + 1));
        yv.y = xv.y * w * rsqrtf((float)(dg.y + 1));
        yv.z = xv.z * w * rsqrtf((float)(dg.z + 1));
        yv.w = xv.w * w * rsqrtf((float)(dg.w + 1));
        reinterpret_cast<float4*>(g_y)[i] = yv;
    }
}
__global__ void k_node_tail(const float* __restrict__ x,
                            const float* __restrict__ W, int n4, int n) {
    int i = n4 * 4 + blockIdx.x * blockDim.x + threadIdx.x;
    if (i < n) {
        g_y[i] = x[i] * __ldg(W) * rsqrtf((float)(g_ideg[i] + 1));
    }
}

// ---------------------------------------------------------------------------
// Scatter: 4 edges/thread. Gathers issued before REDs (MLP=4 per thread).
__global__ void k_scatter(const int* __restrict__ src,
                          const int* __restrict__ dst, int e4, int e) {
    int i = blockIdx.x * blockDim.x + threadIdx.x;
    if (i < e4) {
        int4 s = reinterpret_cast<const int4*>(src)[i];
        int4 d = reinterpret_cast<const int4*>(dst)[i];
        float va = __ldg(&g_y[s.x]);
        float vb = __ldg(&g_y[s.y]);
        float vc = __ldg(&g_y[s.z]);
        float vd = __ldg(&g_y[s.w]);
        atomicAdd(&g_S[d.x], va);
        atomicAdd(&g_S[d.y], vb);
        atomicAdd(&g_S[d.z], vc);
        atomicAdd(&g_S[d.w], vd);
    }
    int t = e4 * 4 + i;
    if (i < (e - e4 * 4)) {
        atomicAdd(&g_S[dst[t]], __ldg(&g_y[src[t]]));
    }
}

// ---------------------------------------------------------------------------
// Finalize: out = sigmoid(rsqrt(deg+1)*(S + y) + b); restore ideg==0 / S==0
// entry invariant for the next graph replay (streaming stores, DRAM ~20%).
__global__ void k_final(float* __restrict__ out,
                        const float* __restrict__ b, int n4) {
    int i = blockIdx.x * blockDim.x + threadIdx.x;
    if (i < n4) {
        float bb = __ldg(b);
        int4   dg = reinterpret_cast<const int4*>(g_ideg)[i];
        float4 sv = reinterpret_cast<const float4*>(g_S)[i];
        float4 yv = reinterpret_cast<const float4*>(g_y)[i];
        float4 o;
        float z0 = rsqrtf((float)(dg.x + 1)) * (sv.x + yv.x) + bb;
        float z1 = rsqrtf((float)(dg.y + 1)) * (sv.y + yv.y) + bb;
        float z2 = rsqrtf((float)(dg.z + 1)) * (sv.z + yv.z) + bb;
        float z3 = rsqrtf((float)(dg.w + 1)) * (sv.w + yv.w) + bb;
        o.x = 1.0f / (1.0f + __expf(-z0));
        o.y = 1.0f / (1.0f + __expf(-z1));
        o.z = 1.0f / (1.0f + __expf(-z2));
        o.w = 1.0f / (1.0f + __expf(-z3));
        reinterpret_cast<float4*>(out)[i] = o;
        reinterpret_cast<int4*>(g_ideg)[i]  = make_int4(0, 0, 0, 0);
        reinterpret_cast<float4*>(g_S)[i]   = make_float4(0.f, 0.f, 0.f, 0.f);
    }
}
__global__ void k_final_tail(float* __restrict__ out,
                             const float* __restrict__ b, int n4, int n) {
    int i = n4 * 4 + blockIdx.x * blockDim.x + threadIdx.x;
    if (i < n) {
        float z = rsqrtf((float)(g_ideg[i] + 1)) * (g_S[i] + g_y[i]) + __ldg(b);
        out[i] = 1.0f / (1.0f + __expf(-z));
        g_ideg[i] = 0;
        g_S[i] = 0.0f;
    }
}

// ---------------------------------------------------------------------------
extern "C" void kernel_launch(void* const* d_in, const int* in_sizes, int n_in,
                              void* d_out, int out_size) {
    const float* x    = (const float*)d_in[0];
    const int*   eidx = (const int*)  d_in[1];
    const float* W    = (const float*)d_in[2];
    const float* b    = (const float*)d_in[3];
    float* out = (float*)d_out;

    int n = in_sizes[0];
    int e = in_sizes[1] / 2;
    const int* src = eidx;
    const int* dst = eidx + e;

    int n4 = n / 4;
    int e4 = e / 4;

    const int TPBN = 256;   // node-side kernels
    const int TPBE = 128;   // edge kernels: measured optimum
    int gn4 = (n4 + TPBN - 1) / TPBN;
    int ge4 = (e4 + TPBE - 1) / TPBE;

    k_degree <<<ge4, TPBE>>>(dst, e4, e);
    k_node   <<<gn4, TPBN>>>(x, W, n4);
    if (n % 4) k_node_tail<<<1, 256>>>(x, W, n4, n);
    k_scatter<<<ge4, TPBE>>>(src, dst, e4, e);
    k_final  <<<gn4, TPBN>>>(out, b, n4);
    if (n % 4) k_final_tail<<<1, 256>>>(out, b, n4, n);
}

// round 16
// speedup vs baseline: 1.0098x; 1.0026x over previous
#include <cuda_runtime.h>
#include <cuda_bf16.h>

// GCNConv (1 in/out feature, self-loops, symmetric norm) + sigmoid.
// out[d] = sigmoid( dinv[d]*( SUM_{e:dst=d} dinv[src]*x[src]*W + dinv[d]*x[d]*W ) + b )
//
// FINAL CONVERGED KERNEL (R1-R15; best 384.6us, reproducible ±0.5us).
// Model: edge passes are L1tex-wavefront bound at ~1 wf/cyc/SM:
//   k_scatter = 2 wf/edge (gather+RED) -> ~232us (at chip LTS random-op cap)
//   k_degree  = 1 wf/edge (RED)        -> ~128us (at ATOMG 4-cyc issue floor)
//   node/final/launch gaps             -> ~25us
// Composed floor ~380us; this config achieves ~99% of it.
// Measured optima: TPBE=128, 4 edges/thread, 4 node-elems/thread, discrete
// kernels, no zero pass (__device__ globals zero-init; k_final restores).
// Refuted: persistent fusion (+157us), dst-binning (+275us), smem
// privatization, wider/narrower unrolls, TPB 64/256/512, node 8-wide.

#define MAXN 1048576

__device__ int   g_ideg[MAXN];   // in-degree; ==0 at entry (restored by k_final)
__device__ float g_y[MAXN];      // x * W * rsqrt(deg)
__device__ float g_S[MAXN];      // edge accumulator; ==0 at entry (restored)

// ---------------------------------------------------------------------------
// Degree: 4 edges/thread (one int4 coalesced read), 4 REDs (L2-resident).
__global__ void k_degree(const int* __restrict__ dst, int e4, int e) {
    int i = blockIdx.x * blockDim.x + threadIdx.x;
    if (i < e4) {
        int4 d = reinterpret_cast<const int4*>(dst)[i];
        atomicAdd(&g_ideg[d.x], 1);
        atomicAdd(&g_ideg[d.y], 1);
        atomicAdd(&g_ideg[d.z], 1);
        atomicAdd(&g_ideg[d.w], 1);
    }
    int t = e4 * 4 + i;
    if (i < (e - e4 * 4)) {
        atomicAdd(&g_ideg[dst[t]], 1);
    }
}

// ---------------------------------------------------------------------------
// Per-node: y = x*W*rsqrt(deg+1).  (S already zero; restored by k_final.)
__global__ void k_node(const float* __restrict__ x,
                       const float* __restrict__ W, int n4) {
    int i = blockIdx.x * blockDim.x + threadIdx.x;
    if (i < n4) {
        float w  = __ldg(W);
        int4  dg = reinterpret_cast<const int4*>(g_ideg)[i];
        float4 xv = reinterpret_cast<const float4*>(x)[i];
        float4 yv;
        yv.x = xv.x * w * rsqrtf((float)(dg.x + 1));
        yv.y = xv.y * w * rsqrtf((float)(dg.y + 1));
        yv.z = xv.z * w * rsqrtf((float)(dg.z + 1));
        yv.w = xv.w * w * rsqrtf((float)(dg.w + 1));
        reinterpret_cast<float4*>(g_y)[i] = yv;
    }
}
__global__ void k_node_tail(const float* __restrict__ x,
                            const float* __restrict__ W, int n4, int n) {
    int i = n4 * 4 + blockIdx.x * blockDim.x + threadIdx.x;
    if (i < n) {
        g_y[i] = x[i] * __ldg(W) * rsqrtf((float)(g_ideg[i] + 1));
    }
}

// ---------------------------------------------------------------------------
// Scatter: 4 edges/thread. Gathers issued before REDs (MLP=4 per thread).
__global__ void k_scatter(const int* __restrict__ src,
                          const int* __restrict__ dst, int e4, int e) {
    int i = blockIdx.x * blockDim.x + threadIdx.x;
    if (i < e4) {
        int4 s = reinterpret_cast<const int4*>(src)[i];
        int4 d = reinterpret_cast<const int4*>(dst)[i];
        float va = __ldg(&g_y[s.x]);
        float vb = __ldg(&g_y[s.y]);
        float vc = __ldg(&g_y[s.z]);
        float vd = __ldg(&g_y[s.w]);
        atomicAdd(&g_S[d.x], va);
        atomicAdd(&g_S[d.y], vb);
        atomicAdd(&g_S[d.z], vc);
        atomicAdd(&g_S[d.w], vd);
    }
    int t = e4 * 4 + i;
    if (i < (e - e4 * 4)) {
        atomicAdd(&g_S[dst[t]], __ldg(&g_y[src[t]]));
    }
}

// ---------------------------------------------------------------------------
// Finalize: out = sigmoid(rsqrt(deg+1)*(S + y) + b); restore ideg==0 / S==0
// entry invariant for the next graph replay (streaming stores, DRAM ~20%).
__global__ void k_final(float* __restrict__ out,
                        const float* __restrict__ b, int n4) {
    int i = blockIdx.x * blockDim.x + threadIdx.x;
    if (i < n4) {
        float bb = __ldg(b);
        int4   dg = reinterpret_cast<const int4*>(g_ideg)[i];
        float4 sv = reinterpret_cast<const float4*>(g_S)[i];
        float4 yv = reinterpret_cast<const float4*>(g_y)[i];
        float4 o;
        float z0 = rsqrtf((float)(dg.x + 1)) * (sv.x + yv.x) + bb;
        float z1 = rsqrtf((float)(dg.y + 1)) * (sv.y + yv.y) + bb;
        float z2 = rsqrtf((float)(dg.z + 1)) * (sv.z + yv.z) + bb;
        float z3 = rsqrtf((float)(dg.w + 1)) * (sv.w + yv.w) + bb;
        o.x = 1.0f / (1.0f + __expf(-z0));
        o.y = 1.0f / (1.0f + __expf(-z1));
        o.z = 1.0f / (1.0f + __expf(-z2));
        o.w = 1.0f / (1.0f + __expf(-z3));
        reinterpret_cast<float4*>(out)[i] = o;
        reinterpret_cast<int4*>(g_ideg)[i]  = make_int4(0, 0, 0, 0);
        reinterpret_cast<float4*>(g_S)[i]   = make_float4(0.f, 0.f, 0.f, 0.f);
    }
}
__global__ void k_final_tail(float* __restrict__ out,
                             const float* __restrict__ b, int n4, int n) {
    int i = n4 * 4 + blockIdx.x * blockDim.x + threadIdx.x;
    if (i < n) {
        float z = rsqrtf((float)(g_ideg[i] + 1)) * (g_S[i] + g_y[i]) + __ldg(b);
        out[i] = 1.0f / (1.0f + __expf(-z));
        g_ideg[i] = 0;
        g_S[i] = 0.0f;
    }
}

// ---------------------------------------------------------------------------
extern "C" void kernel_launch(void* const* d_in, const int* in_sizes, int n_in,
                              void* d_out, int out_size) {
    const float* x    = (const float*)d_in[0];
    const int*   eidx = (const int*)  d_in[1];
    const float* W    = (const float*)d_in[2];
    const float* b    = (const float*)d_in[3];
    float* out = (float*)d_out;

    int n = in_sizes[0];
    int e = in_sizes[1] / 2;
    const int* src = eidx;
    const int* dst = eidx + e;

    int n4 = n / 4;
    int e4 = e / 4;

    const int TPBN = 256;   // node-side kernels
    const int TPBE = 128;   // edge kernels: measured optimum
    int gn4 = (n4 + TPBN - 1) / TPBN;
    int ge4 = (e4 + TPBE - 1) / TPBE;

    k_degree <<<ge4, TPBE>>>(dst, e4, e);
    k_node   <<<gn4, TPBN>>>(x, W, n4);
    if (n % 4) k_node_tail<<<1, 256>>>(x, W, n4, n);
    k_scatter<<<ge4, TPBE>>>(src, dst, e4, e);
    k_final  <<<gn4, TPBN>>>(out, b, n4);
    if (n % 4) k_final_tail<<<1, 256>>>(out, b, n4, n);
}